// round 1
// baseline (speedup 1.0000x reference)
#include <cuda_runtime.h>

#define BATCH 2
#define SEQ   2048
#define EMB   1024
#define NH    16
#define DHEAD 64
#define HIDG  256
#define MROWS (BATCH*SEQ)   // 4096

// -------- scratch (static device globals; no allocation at runtime) --------
__device__ float g_q[BATCH*SEQ*EMB];
__device__ float g_k[BATCH*SEQ*EMB];
__device__ float g_v[BATCH*SEQ*EMB];
__device__ float g_ctx[BATCH*SEQ*EMB];
__device__ float g_p[(size_t)BATCH*NH*SEQ*SEQ];   // 512 MB unnormalized probs
__device__ float g_l[BATCH*NH*SEQ];               // softmax denominators
__device__ float g_sw[BATCH*NH];                  // per-head sync gate

#define F4C(v,i) ((i)==0?(v).x:((i)==1?(v).y:((i)==2?(v).z:(v).w)))

// ---------------------------------------------------------------------------
// Sync gate: sw = sigmoid(relu(sf @ Ws1 + bs1) @ Ws2 + bs2)   [B,H]
// ---------------------------------------------------------------------------
__global__ void gate_kernel(const float* __restrict__ sf,
                            const float* __restrict__ Ws1, const float* __restrict__ bs1,
                            const float* __restrict__ Ws2, const float* __restrict__ bs2)
{
    __shared__ float h1[BATCH*HIDG];
    int tid = threadIdx.x;
    for (int idx = tid; idx < BATCH*HIDG; idx += blockDim.x) {
        int b = idx / HIDG, j = idx % HIDG;
        float acc = bs1[j];
        for (int k = 0; k < EMB; k++)
            acc += sf[b*EMB + k] * Ws1[k*HIDG + j];
        h1[idx] = fmaxf(acc, 0.0f);
    }
    __syncthreads();
    if (tid < BATCH*NH) {
        int b = tid / NH, h = tid % NH;
        float acc = bs2[h];
        for (int j = 0; j < HIDG; j++)
            acc += h1[b*HIDG + j] * Ws2[j*NH + h];
        g_sw[tid] = 1.0f / (1.0f + expf(-acc));
    }
}

// ---------------------------------------------------------------------------
// Tiled SGEMM: C[M,N] = X[M,K] @ W[K,N] + bias.  64x64 tile, 256 thr, 4x4/thr.
// M,N div by 64; K div by 32.
// ---------------------------------------------------------------------------
__global__ void __launch_bounds__(256) gemm64_kernel(
    const float* __restrict__ X, const float* __restrict__ W,
    const float* __restrict__ bias, float* __restrict__ C,
    int M, int N, int K)
{
    __shared__ float Xt[64*36];   // [row][k], pitch 36
    __shared__ float Wt[32*64];   // [k][col], pitch 64
    const int tid = threadIdx.x;
    const int tx = tid & 15, ty = tid >> 4;
    const int n0 = blockIdx.x * 64, m0 = blockIdx.y * 64;
    float acc[4][4] = {};

    for (int k0 = 0; k0 < K; k0 += 32) {
        #pragma unroll
        for (int t = tid; t < 512; t += 256) {
            int r = t >> 3, c4 = (t & 7) << 2;
            *(float4*)&Xt[r*36 + c4] =
                *(const float4*)&X[(size_t)(m0 + r)*K + k0 + c4];
        }
        #pragma unroll
        for (int t = tid; t < 512; t += 256) {
            int r = t >> 4, c4 = (t & 15) << 2;
            *(float4*)&Wt[r*64 + c4] =
                *(const float4*)&W[(size_t)(k0 + r)*N + n0 + c4];
        }
        __syncthreads();
        #pragma unroll
        for (int kk = 0; kk < 32; kk += 4) {
            float4 a[4], bw[4];
            #pragma unroll
            for (int r = 0; r < 4; r++)
                a[r] = *(const float4*)&Xt[(4*ty + r)*36 + kk];
            #pragma unroll
            for (int kq = 0; kq < 4; kq++)
                bw[kq] = *(const float4*)&Wt[(kk + kq)*64 + 4*tx];
            #pragma unroll
            for (int r = 0; r < 4; r++)
                #pragma unroll
                for (int c = 0; c < 4; c++)
                    acc[r][c] += F4C(a[r],0)*F4C(bw[0],c)
                               + F4C(a[r],1)*F4C(bw[1],c)
                               + F4C(a[r],2)*F4C(bw[2],c)
                               + F4C(a[r],3)*F4C(bw[3],c);
        }
        __syncthreads();
    }

    float4 bv = *(const float4*)&bias[n0 + 4*tx];
    #pragma unroll
    for (int r = 0; r < 4; r++) {
        float4 o;
        o.x = acc[r][0] + bv.x;  o.y = acc[r][1] + bv.y;
        o.z = acc[r][2] + bv.z;  o.w = acc[r][3] + bv.w;
        *(float4*)&C[(size_t)(m0 + 4*ty + r)*N + n0 + 4*tx] = o;
    }
}

// ---------------------------------------------------------------------------
// Attention: one block = (b, h, 64-row i-tile).
// Single pass over j: S = Qt Kt^T (scale folded into Qt), p = exp(S),
// l += rowsum(p), p -> g_p scratch, ctx += p @ Vt; finalize ctx /= l.
// ---------------------------------------------------------------------------
#define ATTN_SMEM_FLOATS (64*64 + 64*68 + 64*64 + 64*68 + 64)
#define ATTN_SMEM_BYTES  (ATTN_SMEM_FLOATS * 4)

__global__ void __launch_bounds__(256) attn_kernel()
{
    extern __shared__ float sm[];
    float* Qt   = sm;                    // [i][d]  pitch 64
    float* Kt   = Qt + 64*64;            // [j][d]  pitch 68
    float* Vt   = Kt + 64*68;            // [j][d]  pitch 64
    float* Pt   = Vt + 64*64;            // [i][j]  pitch 68
    float* l_sm = Pt + 64*68;            // [64]

    const int tid = threadIdx.x;
    const int tx = tid & 15, ty = tid >> 4;
    const int it = blockIdx.x, h = blockIdx.y, b = blockIdx.z;
    const int i0 = it * 64;

    const float sl = g_sw[b*NH + h] * 0.125f;  // sw / sqrt(DH)

    const float* qbase = g_q + ((size_t)(b*SEQ + i0))*EMB + h*DHEAD;
    const float* kbase = g_k + ((size_t)(b*SEQ))*EMB + h*DHEAD;
    const float* vbase = g_v + ((size_t)(b*SEQ))*EMB + h*DHEAD;
    float*       pbase = g_p + ((size_t)(b*NH + h)*SEQ + i0)*SEQ;

    // Load Q tile, scaled
    #pragma unroll
    for (int t = tid; t < 1024; t += 256) {
        int r = t >> 4, c4 = (t & 15) << 2;
        float4 v = *(const float4*)&qbase[(size_t)r*EMB + c4];
        v.x *= sl; v.y *= sl; v.z *= sl; v.w *= sl;
        *(float4*)&Qt[r*64 + c4] = v;
    }
    if (tid < 64) l_sm[tid] = 0.0f;

    float ctxa[4][4] = {};
    __syncthreads();

    for (int j0 = 0; j0 < SEQ; j0 += 64) {
        // load K, V tiles
        #pragma unroll
        for (int t = tid; t < 1024; t += 256) {
            int r = t >> 4, c4 = (t & 15) << 2;
            *(float4*)&Kt[r*68 + c4] =
                *(const float4*)&kbase[(size_t)(j0 + r)*EMB + c4];
            *(float4*)&Vt[r*64 + c4] =
                *(const float4*)&vbase[(size_t)(j0 + r)*EMB + c4];
        }
        __syncthreads();

        // S = Qt @ Kt^T  (4x4 per thread)
        float acc[4][4] = {};
        #pragma unroll
        for (int kk = 0; kk < 64; kk += 4) {
            float4 a[4], bb[4];
            #pragma unroll
            for (int r = 0; r < 4; r++)
                a[r] = *(const float4*)&Qt[(4*ty + r)*64 + kk];
            #pragma unroll
            for (int c = 0; c < 4; c++)
                bb[c] = *(const float4*)&Kt[(4*tx + c)*68 + kk];
            #pragma unroll
            for (int r = 0; r < 4; r++)
                #pragma unroll
                for (int c = 0; c < 4; c++)
                    acc[r][c] += F4C(a[r],0)*F4C(bb[c],0)
                               + F4C(a[r],1)*F4C(bb[c],1)
                               + F4C(a[r],2)*F4C(bb[c],2)
                               + F4C(a[r],3)*F4C(bb[c],3);
        }

        // p = exp(S); accumulate denominators; stash p in smem + gmem scratch
        #pragma unroll
        for (int r = 0; r < 4; r++) {
            float rs = 0.0f;
            #pragma unroll
            for (int c = 0; c < 4; c++) {
                float p = __expf(acc[r][c]);
                acc[r][c] = p;
                rs += p;
            }
            atomicAdd(&l_sm[4*ty + r], rs);
            float4 pv;
            pv.x = acc[r][0]; pv.y = acc[r][1]; pv.z = acc[r][2]; pv.w = acc[r][3];
            *(float4*)&Pt[(4*ty + r)*68 + 4*tx] = pv;
            *(float4*)&pbase[(size_t)(4*ty + r)*SEQ + j0 + 4*tx] = pv;
        }
        __syncthreads();

        // ctx += Pt @ Vt
        #pragma unroll 16
        for (int j = 0; j < 64; j++) {
            float pr[4];
            #pragma unroll
            for (int r = 0; r < 4; r++)
                pr[r] = Pt[(4*ty + r)*68 + j];
            float4 vv = *(const float4*)&Vt[j*64 + 4*tx];
            #pragma unroll
            for (int r = 0; r < 4; r++) {
                ctxa[r][0] += pr[r]*vv.x;
                ctxa[r][1] += pr[r]*vv.y;
                ctxa[r][2] += pr[r]*vv.z;
                ctxa[r][3] += pr[r]*vv.w;
            }
        }
        __syncthreads();
    }

    // finalize: ctx /= l, store; store l
    float* cbase = g_ctx + ((size_t)(b*SEQ + i0))*EMB + h*DHEAD;
    #pragma unroll
    for (int r = 0; r < 4; r++) {
        float linv = 1.0f / l_sm[4*ty + r];
        float4 o;
        o.x = ctxa[r][0]*linv; o.y = ctxa[r][1]*linv;
        o.z = ctxa[r][2]*linv; o.w = ctxa[r][3]*linv;
        *(float4*)&cbase[(size_t)(4*ty + r)*EMB + 4*tx] = o;
    }
    if (tid < 64)
        g_l[(size_t)(b*NH + h)*SEQ + i0 + tid] = l_sm[tid];
}

// ---------------------------------------------------------------------------
// mean[b,i,j] = (1/H) * sum_h g_p[b,h,i,j] / g_l[b,h,i]
// grid (SEQ, BATCH), 256 threads; each thread handles 8 j's (2 float4).
// ---------------------------------------------------------------------------
__global__ void __launch_bounds__(256) mean_kernel(float* __restrict__ out_mean)
{
    const int i = blockIdx.x, b = blockIdx.y;
    const int tid = threadIdx.x;
    __shared__ float inv[NH];
    if (tid < NH)
        inv[tid] = 1.0f / (g_l[(size_t)(b*NH + tid)*SEQ + i] * (float)NH);
    __syncthreads();

    float4 a0 = {0,0,0,0}, a1 = {0,0,0,0};
    #pragma unroll
    for (int h = 0; h < NH; h++) {
        const float4* p4 = (const float4*)&g_p[((size_t)(b*NH + h)*SEQ + i)*SEQ];
        float4 v0 = p4[tid];
        float4 v1 = p4[tid + 256];
        float w = inv[h];
        a0.x += v0.x*w; a0.y += v0.y*w; a0.z += v0.z*w; a0.w += v0.w*w;
        a1.x += v1.x*w; a1.y += v1.y*w; a1.z += v1.z*w; a1.w += v1.w*w;
    }
    float4* dst = (float4*)&out_mean[((size_t)(b*SEQ) + i)*SEQ];
    dst[tid]       = a0;
    dst[tid + 256] = a1;
}

// ---------------------------------------------------------------------------
extern "C" void kernel_launch(void* const* d_in, const int* in_sizes, int n_in,
                              void* d_out, int out_size)
{
    const float* x   = (const float*)d_in[0];
    const float* sf  = (const float*)d_in[1];
    const float* Wq  = (const float*)d_in[2];  const float* bq  = (const float*)d_in[3];
    const float* Wk  = (const float*)d_in[4];  const float* bk  = (const float*)d_in[5];
    const float* Wv  = (const float*)d_in[6];  const float* bv  = (const float*)d_in[7];
    const float* Ws1 = (const float*)d_in[8];  const float* bs1 = (const float*)d_in[9];
    const float* Ws2 = (const float*)d_in[10]; const float* bs2 = (const float*)d_in[11];
    const float* Wo  = (const float*)d_in[12]; const float* bo  = (const float*)d_in[13];

    float* out      = (float*)d_out;                       // [B,S,E]
    float* out_mean = out + (size_t)BATCH*SEQ*EMB;         // [B,S,S]

    float *qp, *kp, *vp, *cp;
    cudaGetSymbolAddress((void**)&qp, g_q);
    cudaGetSymbolAddress((void**)&kp, g_k);
    cudaGetSymbolAddress((void**)&vp, g_v);
    cudaGetSymbolAddress((void**)&cp, g_ctx);

    cudaFuncSetAttribute(attn_kernel,
                         cudaFuncAttributeMaxDynamicSharedMemorySize,
                         ATTN_SMEM_BYTES);

    // 1) sync gate
    gate_kernel<<<1, 256>>>(sf, Ws1, bs1, Ws2, bs2);

    // 2) QKV projections
    dim3 gg(EMB/64, MROWS/64);
    gemm64_kernel<<<gg, 256>>>(x, Wq, bq, qp, MROWS, EMB, EMB);
    gemm64_kernel<<<gg, 256>>>(x, Wk, bk, kp, MROWS, EMB, EMB);
    gemm64_kernel<<<gg, 256>>>(x, Wv, bv, vp, MROWS, EMB, EMB);

    // 3) attention (ctx, p scratch, denominators)
    attn_kernel<<<dim3(SEQ/64, NH, BATCH), 256, ATTN_SMEM_BYTES>>>();

    // 4) head-mean of attention probs
    mean_kernel<<<dim3(SEQ, BATCH), 256>>>(out_mean);

    // 5) output projection
    gemm64_kernel<<<gg, 256>>>(cp, Wo, bo, out, MROWS, EMB, EMB);
}

// round 15
// speedup vs baseline: 2.4176x; 2.4176x over previous
#include <cuda_runtime.h>

#define BATCH 2
#define SEQ   2048
#define EMB   1024
#define NH    16
#define DHEAD 64
#define HIDG  256
#define MROWS (BATCH*SEQ)   // 4096

// -------- scratch (static device globals; no allocation at runtime) --------
__device__ float g_q[BATCH*SEQ*EMB];
__device__ float g_k[BATCH*SEQ*EMB];
__device__ float g_v[BATCH*SEQ*EMB];
__device__ float g_ctx[BATCH*SEQ*EMB];
__device__ float g_p[(size_t)BATCH*NH*SEQ*SEQ];   // 512 MB unnormalized probs
__device__ float g_l[BATCH*NH*SEQ];               // softmax denominators
__device__ float g_sw[BATCH*NH];                  // per-head sync gate

// ---------------------------------------------------------------------------
// helpers
// ---------------------------------------------------------------------------
__device__ __forceinline__ unsigned f2tf(float f) {
    unsigned u;
    asm("cvt.rna.tf32.f32 %0, %1;" : "=r"(u) : "f"(f));
    return u;
}

__device__ __forceinline__ void mma_tf32(float& d0, float& d1, float& d2, float& d3,
                                         unsigned a0, unsigned a1, unsigned a2, unsigned a3,
                                         unsigned b0, unsigned b1)
{
    asm volatile(
        "mma.sync.aligned.m16n8k8.row.col.f32.tf32.tf32.f32 "
        "{%0,%1,%2,%3}, {%4,%5,%6,%7}, {%8,%9}, {%0,%1,%2,%3};"
        : "+f"(d0), "+f"(d1), "+f"(d2), "+f"(d3)
        : "r"(a0), "r"(a1), "r"(a2), "r"(a3), "r"(b0), "r"(b1));
}

// ---------------------------------------------------------------------------
// Sync gate: sw = sigmoid(relu(sf @ Ws1 + bs1) @ Ws2 + bs2)   [B,H]
// ---------------------------------------------------------------------------
__global__ void gate_kernel(const float* __restrict__ sf,
                            const float* __restrict__ Ws1, const float* __restrict__ bs1,
                            const float* __restrict__ Ws2, const float* __restrict__ bs2)
{
    __shared__ float h1[BATCH*HIDG];
    int tid = threadIdx.x;
    for (int idx = tid; idx < BATCH*HIDG; idx += blockDim.x) {
        int b = idx / HIDG, j = idx % HIDG;
        float acc = bs1[j];
        for (int k = 0; k < EMB; k++)
            acc += sf[b*EMB + k] * Ws1[k*HIDG + j];
        h1[idx] = fmaxf(acc, 0.0f);
    }
    __syncthreads();
    if (tid < BATCH*NH) {
        int b = tid / NH, h = tid % NH;
        float acc = bs2[h];
        for (int j = 0; j < HIDG; j++)
            acc += h1[b*HIDG + j] * Ws2[j*NH + h];
        g_sw[tid] = 1.0f / (1.0f + expf(-acc));
    }
}

// ---------------------------------------------------------------------------
// TF32 tensor-core GEMM body: C[M,N] = X[M,K] @ W[K,N] + bias
// Block tile 128x128, BK=32, 256 threads (8 warps as 2(m) x 4(n)),
// warp tile 64x32 = 4x4 m16n8k8 mma tiles.
// ---------------------------------------------------------------------------
#define GPA 36    // A smem pitch (floats): bank-conflict-free fragment loads
#define GPB 136   // B smem pitch

__device__ __forceinline__ void gemm_tf32_body(
    const float* __restrict__ X, const float* __restrict__ W,
    const float* __restrict__ bias, float* __restrict__ C,
    int M, int N, int K)
{
    __shared__ unsigned As[128*GPA];
    __shared__ unsigned Bs[32*GPB];

    const int tid  = threadIdx.x;
    const int warp = tid >> 5, lane = tid & 31;
    const int g = lane >> 2, t = lane & 3;
    const int wm = warp & 1, wn = warp >> 1;      // 2 x 4 warp grid
    const int m0 = blockIdx.y * 128, n0 = blockIdx.x * 128;

    const int ar_row = tid >> 3, ar_c4 = (tid & 7) << 2;    // A: 4 passes of 32 rows
    const int br_row = tid >> 5, br_c4 = (tid & 31) << 2;   // B: 4 passes of 8 rows

    float4 ar[4], br[4];
    float acc[4][4][4] = {};

    // prologue: load first tile to regs
    #pragma unroll
    for (int p = 0; p < 4; p++)
        ar[p] = *(const float4*)&X[(size_t)(m0 + ar_row + p*32)*K + ar_c4];
    #pragma unroll
    for (int p = 0; p < 4; p++)
        br[p] = *(const float4*)&W[(size_t)(br_row + p*8)*N + n0 + br_c4];

    for (int k0 = 0; k0 < K; k0 += 32) {
        // store regs -> smem (tf32 rounded)
        #pragma unroll
        for (int p = 0; p < 4; p++) {
            unsigned* d = &As[(ar_row + p*32)*GPA + ar_c4];
            d[0] = f2tf(ar[p].x); d[1] = f2tf(ar[p].y);
            d[2] = f2tf(ar[p].z); d[3] = f2tf(ar[p].w);
        }
        #pragma unroll
        for (int p = 0; p < 4; p++) {
            unsigned* d = &Bs[(br_row + p*8)*GPB + br_c4];
            d[0] = f2tf(br[p].x); d[1] = f2tf(br[p].y);
            d[2] = f2tf(br[p].z); d[3] = f2tf(br[p].w);
        }
        __syncthreads();

        // prefetch next tile
        if (k0 + 32 < K) {
            #pragma unroll
            for (int p = 0; p < 4; p++)
                ar[p] = *(const float4*)&X[(size_t)(m0 + ar_row + p*32)*K + k0 + 32 + ar_c4];
            #pragma unroll
            for (int p = 0; p < 4; p++)
                br[p] = *(const float4*)&W[(size_t)(k0 + 32 + br_row + p*8)*N + n0 + br_c4];
        }

        // compute 4 k-steps of 8
        #pragma unroll
        for (int ks = 0; ks < 4; ks++) {
            unsigned af[4][4], bf[4][2];
            #pragma unroll
            for (int mt = 0; mt < 4; mt++) {
                int row = wm*64 + mt*16 + g;
                af[mt][0] = As[row*GPA + ks*8 + t];
                af[mt][1] = As[(row+8)*GPA + ks*8 + t];
                af[mt][2] = As[row*GPA + ks*8 + t + 4];
                af[mt][3] = As[(row+8)*GPA + ks*8 + t + 4];
            }
            #pragma unroll
            for (int nt = 0; nt < 4; nt++) {
                int col = wn*32 + nt*8 + g;
                bf[nt][0] = Bs[(ks*8 + t)*GPB + col];
                bf[nt][1] = Bs[(ks*8 + t + 4)*GPB + col];
            }
            #pragma unroll
            for (int mt = 0; mt < 4; mt++)
                #pragma unroll
                for (int nt = 0; nt < 4; nt++)
                    mma_tf32(acc[mt][nt][0], acc[mt][nt][1], acc[mt][nt][2], acc[mt][nt][3],
                             af[mt][0], af[mt][1], af[mt][2], af[mt][3],
                             bf[nt][0], bf[nt][1]);
        }
        __syncthreads();
    }

    // epilogue: add bias, store
    #pragma unroll
    for (int nt = 0; nt < 4; nt++) {
        int col = n0 + wn*32 + nt*8 + 2*t;
        float2 bv = *(const float2*)&bias[col];
        #pragma unroll
        for (int mt = 0; mt < 4; mt++) {
            int row = m0 + wm*64 + mt*16 + g;
            float2 o0 = { acc[mt][nt][0] + bv.x, acc[mt][nt][1] + bv.y };
            float2 o1 = { acc[mt][nt][2] + bv.x, acc[mt][nt][3] + bv.y };
            *(float2*)&C[(size_t)row*N + col]     = o0;
            *(float2*)&C[(size_t)(row+8)*N + col] = o1;
        }
    }
}

// single GEMM (output projection)
__global__ void __launch_bounds__(256) gemm_tf32_kernel(
    const float* __restrict__ X, const float* __restrict__ W,
    const float* __restrict__ bias, float* __restrict__ C,
    int M, int N, int K)
{
    gemm_tf32_body(X, W, bias, C, M, N, K);
}

// fused QKV: blockIdx.z selects projection (0=Q, 1=K, 2=V)
__global__ void __launch_bounds__(256) gemm_qkv_kernel(
    const float* __restrict__ X,
    const float* __restrict__ Wq, const float* __restrict__ bq,
    const float* __restrict__ Wk, const float* __restrict__ bk,
    const float* __restrict__ Wv, const float* __restrict__ bv,
    float* __restrict__ q, float* __restrict__ k, float* __restrict__ v)
{
    const float* W; const float* bias; float* C;
    if (blockIdx.z == 0)      { W = Wq; bias = bq; C = q; }
    else if (blockIdx.z == 1) { W = Wk; bias = bk; C = k; }
    else                      { W = Wv; bias = bv; C = v; }
    gemm_tf32_body(X, W, bias, C, MROWS, EMB, EMB);
}

// ---------------------------------------------------------------------------
// Attention with tf32 tensor cores.
// Block = (b, h, 128-row i-tile), 256 threads (8 warps as 4(m) x 2(n)).
// Per j-tile of 64: S = Q K^T (mma), p = rna_tf32(exp(sl*S)) used consistently
// for row sums, smem P, g_p scratch, and the PV MMA. Finalize ctx /= l.
// ---------------------------------------------------------------------------
#define PQ 68
#define PK 68
#define PV 72
#define PP 68
#define ATTN_SMEM_BYTES ((128*PQ + 64*PK + 64*PV + 128*PP + 128) * 4)

__global__ void __launch_bounds__(256) attn_kernel()
{
    extern __shared__ unsigned char smraw[];
    unsigned* Qs = (unsigned*)smraw;               // [128][PQ] tf32 bits
    unsigned* Ks = Qs + 128*PQ;                    // [64][PK]
    unsigned* Vs = Ks + 64*PK;                     // [64][PV]
    float*    Ps = (float*)(Vs + 64*PV);           // [128][PP] probs (tf32 values)
    float*  l_sm = Ps + 128*PP;                    // [128]

    const int tid  = threadIdx.x;
    const int warp = tid >> 5, lane = tid & 31;
    const int g = lane >> 2, t = lane & 3;
    const int wm = warp & 3, wn = warp >> 2;       // 4 x 2 warp grid
    const int i0 = blockIdx.x * 128, h = blockIdx.y, b = blockIdx.z;

    const float sl = g_sw[b*NH + h] * 0.125f;      // sw / sqrt(DH)

    const float* qbase = g_q + ((size_t)(b*SEQ + i0))*EMB + h*DHEAD;
    const float* kbase = g_k + ((size_t)(b*SEQ))*EMB + h*DHEAD;
    const float* vbase = g_v + ((size_t)(b*SEQ))*EMB + h*DHEAD;
    float*       pbase = g_p + ((size_t)(b*NH + h)*SEQ + i0)*SEQ;

    // load Q tile [128][64] -> tf32 smem
    #pragma unroll
    for (int p = 0; p < 8; p++) {
        int idx = tid + p*256;
        int r = idx >> 4, c4 = (idx & 15) << 2;
        float4 v = *(const float4*)&qbase[(size_t)r*EMB + c4];
        unsigned* d = &Qs[r*PQ + c4];
        d[0] = f2tf(v.x); d[1] = f2tf(v.y); d[2] = f2tf(v.z); d[3] = f2tf(v.w);
    }
    if (tid < 128) l_sm[tid] = 0.0f;

    float cacc[2][4][4] = {};    // ctx accumulators (mt, nt, c)
    float ls[4] = {};            // row-sum accumulators
    __syncthreads();

    for (int j0 = 0; j0 < SEQ; j0 += 64) {
        // load K, V tiles [64][64]
        #pragma unroll
        for (int p = 0; p < 4; p++) {
            int idx = tid + p*256;
            int r = idx >> 4, c4 = (idx & 15) << 2;
            float4 kv = *(const float4*)&kbase[(size_t)(j0 + r)*EMB + c4];
            float4 vv = *(const float4*)&vbase[(size_t)(j0 + r)*EMB + c4];
            unsigned* dk = &Ks[r*PK + c4];
            dk[0] = f2tf(kv.x); dk[1] = f2tf(kv.y); dk[2] = f2tf(kv.z); dk[3] = f2tf(kv.w);
            unsigned* dv = &Vs[r*PV + c4];
            dv[0] = f2tf(vv.x); dv[1] = f2tf(vv.y); dv[2] = f2tf(vv.z); dv[3] = f2tf(vv.w);
        }
        __syncthreads();

        // S = Q K^T : warp tile 32(i) x 32(j) = 2 x 4 mma tiles, k = 64
        float sacc[2][4][4] = {};
        #pragma unroll
        for (int ks = 0; ks < 8; ks++) {
            unsigned af[2][4], bf[4][2];
            #pragma unroll
            for (int mt = 0; mt < 2; mt++) {
                int row = wm*32 + mt*16 + g;
                af[mt][0] = Qs[row*PQ + ks*8 + t];
                af[mt][1] = Qs[(row+8)*PQ + ks*8 + t];
                af[mt][2] = Qs[row*PQ + ks*8 + t + 4];
                af[mt][3] = Qs[(row+8)*PQ + ks*8 + t + 4];
            }
            #pragma unroll
            for (int nt = 0; nt < 4; nt++) {
                int jc = wn*32 + nt*8 + g;
                bf[nt][0] = Ks[jc*PK + ks*8 + t];
                bf[nt][1] = Ks[jc*PK + ks*8 + t + 4];
            }
            #pragma unroll
            for (int mt = 0; mt < 2; mt++)
                #pragma unroll
                for (int nt = 0; nt < 4; nt++)
                    mma_tf32(sacc[mt][nt][0], sacc[mt][nt][1], sacc[mt][nt][2], sacc[mt][nt][3],
                             af[mt][0], af[mt][1], af[mt][2], af[mt][3],
                             bf[nt][0], bf[nt][1]);
        }

        // p = exp(sl*S), rounded once to tf32 and used consistently everywhere
        #pragma unroll
        for (int mt = 0; mt < 2; mt++) {
            #pragma unroll
            for (int nt = 0; nt < 4; nt++) {
                float p0 = __uint_as_float(f2tf(__expf(sacc[mt][nt][0] * sl)));
                float p1 = __uint_as_float(f2tf(__expf(sacc[mt][nt][1] * sl)));
                float p2 = __uint_as_float(f2tf(__expf(sacc[mt][nt][2] * sl)));
                float p3 = __uint_as_float(f2tf(__expf(sacc[mt][nt][3] * sl)));
                ls[mt*2 + 0] += p0 + p1;
                ls[mt*2 + 1] += p2 + p3;
                int row = wm*32 + mt*16 + g;
                int col = wn*32 + nt*8 + 2*t;
                *(float2*)&Ps[row*PP + col]     = make_float2(p0, p1);
                *(float2*)&Ps[(row+8)*PP + col] = make_float2(p2, p3);
                *(float2*)&pbase[(size_t)row*SEQ + j0 + col]     = make_float2(p0, p1);
                *(float2*)&pbase[(size_t)(row+8)*SEQ + j0 + col] = make_float2(p2, p3);
            }
        }
        __syncthreads();

        // ctx += P V : warp tile 32(i) x 32(d) = 2 x 4 mma tiles, k = 64 (j)
        #pragma unroll
        for (int ks = 0; ks < 8; ks++) {
            unsigned af[2][4], bf[4][2];
            #pragma unroll
            for (int mt = 0; mt < 2; mt++) {
                int row = wm*32 + mt*16 + g;
                af[mt][0] = __float_as_uint(Ps[row*PP + ks*8 + t]);
                af[mt][1] = __float_as_uint(Ps[(row+8)*PP + ks*8 + t]);
                af[mt][2] = __float_as_uint(Ps[row*PP + ks*8 + t + 4]);
                af[mt][3] = __float_as_uint(Ps[(row+8)*PP + ks*8 + t + 4]);
            }
            #pragma unroll
            for (int nt = 0; nt < 4; nt++) {
                int dc = wn*32 + nt*8 + g;
                bf[nt][0] = Vs[(ks*8 + t)*PV + dc];
                bf[nt][1] = Vs[(ks*8 + t + 4)*PV + dc];
            }
            #pragma unroll
            for (int mt = 0; mt < 2; mt++)
                #pragma unroll
                for (int nt = 0; nt < 4; nt++)
                    mma_tf32(cacc[mt][nt][0], cacc[mt][nt][1], cacc[mt][nt][2], cacc[mt][nt][3],
                             af[mt][0], af[mt][1], af[mt][2], af[mt][3],
                             bf[nt][0], bf[nt][1]);
        }
        __syncthreads();
    }

    // reduce row sums across the quad (t lanes), accumulate into l_sm
    #pragma unroll
    for (int i = 0; i < 4; i++) {
        float v = ls[i];
        v += __shfl_xor_sync(0xffffffffu, v, 1);
        v += __shfl_xor_sync(0xffffffffu, v, 2);
        ls[i] = v;
    }
    if (t == 0) {
        #pragma unroll
        for (int mt = 0; mt < 2; mt++) {
            int row = wm*32 + mt*16 + g;
            atomicAdd(&l_sm[row],     ls[mt*2 + 0]);
            atomicAdd(&l_sm[row + 8], ls[mt*2 + 1]);
        }
    }
    __syncthreads();

    // finalize: ctx /= l, store ctx and l
    float* cbase = g_ctx + ((size_t)(b*SEQ + i0))*EMB + h*DHEAD;
    #pragma unroll
    for (int mt = 0; mt < 2; mt++) {
        int row = wm*32 + mt*16 + g;
        float inv0 = 1.0f / l_sm[row];
        float inv1 = 1.0f / l_sm[row + 8];
        #pragma unroll
        for (int nt = 0; nt < 4; nt++) {
            int col = wn*32 + nt*8 + 2*t;
            float2 o0 = { cacc[mt][nt][0]*inv0, cacc[mt][nt][1]*inv0 };
            float2 o1 = { cacc[mt][nt][2]*inv1, cacc[mt][nt][3]*inv1 };
            *(float2*)&cbase[(size_t)row*EMB + col]     = o0;
            *(float2*)&cbase[(size_t)(row+8)*EMB + col] = o1;
        }
    }
    if (tid < 128)
        g_l[(size_t)(b*NH + h)*SEQ + i0 + tid] = l_sm[tid];
}

// ---------------------------------------------------------------------------
// mean[b,i,j] = (1/H) * sum_h g_p[b,h,i,j] / g_l[b,h,i]
// ---------------------------------------------------------------------------
__global__ void __launch_bounds__(256) mean_kernel(float* __restrict__ out_mean)
{
    const int i = blockIdx.x, b = blockIdx.y;
    const int tid = threadIdx.x;
    __shared__ float inv[NH];
    if (tid < NH)
        inv[tid] = 1.0f / (g_l[(size_t)(b*NH + tid)*SEQ + i] * (float)NH);
    __syncthreads();

    float4 a0 = {0,0,0,0}, a1 = {0,0,0,0};
    #pragma unroll
    for (int h = 0; h < NH; h++) {
        const float4* p4 = (const float4*)&g_p[((size_t)(b*NH + h)*SEQ + i)*SEQ];
        float4 v0 = p4[tid];
        float4 v1 = p4[tid + 256];
        float w = inv[h];
        a0.x += v0.x*w; a0.y += v0.y*w; a0.z += v0.z*w; a0.w += v0.w*w;
        a1.x += v1.x*w; a1.y += v1.y*w; a1.z += v1.z*w; a1.w += v1.w*w;
    }
    float4* dst = (float4*)&out_mean[((size_t)(b*SEQ) + i)*SEQ];
    dst[tid]       = a0;
    dst[tid + 256] = a1;
}

// ---------------------------------------------------------------------------
extern "C" void kernel_launch(void* const* d_in, const int* in_sizes, int n_in,
                              void* d_out, int out_size)
{
    const float* x   = (const float*)d_in[0];
    const float* sf  = (const float*)d_in[1];
    const float* Wq  = (const float*)d_in[2];  const float* bq  = (const float*)d_in[3];
    const float* Wk  = (const float*)d_in[4];  const float* bk  = (const float*)d_in[5];
    const float* Wv  = (const float*)d_in[6];  const float* bv  = (const float*)d_in[7];
    const float* Ws1 = (const float*)d_in[8];  const float* bs1 = (const float*)d_in[9];
    const float* Ws2 = (const float*)d_in[10]; const float* bs2 = (const float*)d_in[11];
    const float* Wo  = (const float*)d_in[12]; const float* bo  = (const float*)d_in[13];

    float* out      = (float*)d_out;                       // [B,S,E]
    float* out_mean = out + (size_t)BATCH*SEQ*EMB;         // [B,S,S]

    float *qp, *kp, *vp, *cp;
    cudaGetSymbolAddress((void**)&qp, g_q);
    cudaGetSymbolAddress((void**)&kp, g_k);
    cudaGetSymbolAddress((void**)&vp, g_v);
    cudaGetSymbolAddress((void**)&cp, g_ctx);

    cudaFuncSetAttribute(attn_kernel,
                         cudaFuncAttributeMaxDynamicSharedMemorySize,
                         ATTN_SMEM_BYTES);

    // 1) sync gate
    gate_kernel<<<1, 256>>>(sf, Ws1, bs1, Ws2, bs2);

    // 2) fused QKV projections (tf32 tensor cores), one launch
    dim3 gq(EMB/128, MROWS/128, 3);
    gemm_qkv_kernel<<<gq, 256>>>(x, Wq, bq, Wk, bk, Wv, bv, qp, kp, vp);

    // 3) attention (ctx, p scratch, denominators)
    attn_kernel<<<dim3(SEQ/128, NH, BATCH), 256, ATTN_SMEM_BYTES>>>();

    // 4) head-mean of attention probs
    mean_kernel<<<dim3(SEQ, BATCH), 256>>>(out_mean);

    // 5) output projection
    dim3 gg(EMB/128, MROWS/128);
    gemm_tf32_kernel<<<gg, 256>>>(cp, Wo, bo, out, MROWS, EMB, EMB);
}

// round 16
// speedup vs baseline: 3.6050x; 1.4912x over previous
#include <cuda_runtime.h>

#define BATCH 2
#define SEQ   2048
#define EMB   1024
#define NH    16
#define DHEAD 64
#define HIDG  256
#define MROWS (BATCH*SEQ)   // 4096

// -------- scratch (static device globals; no allocation at runtime) --------
__device__ float g_q[BATCH*SEQ*EMB];
__device__ float g_k[BATCH*SEQ*EMB];
__device__ float g_v[BATCH*SEQ*EMB];
__device__ float g_ctx[BATCH*SEQ*EMB];
__device__ float g_p[(size_t)BATCH*NH*SEQ*SEQ];   // 512 MB unnormalized probs
__device__ float g_l[BATCH*NH*SEQ];               // softmax denominators
__device__ float g_sw[BATCH*NH];                  // per-head sync gate

// ---------------------------------------------------------------------------
// helpers
// ---------------------------------------------------------------------------
__device__ __forceinline__ unsigned f2tf(float f) {
    unsigned u;
    asm("cvt.rna.tf32.f32 %0, %1;" : "=r"(u) : "f"(f));
    return u;
}

__device__ __forceinline__ void mma_tf32(float& d0, float& d1, float& d2, float& d3,
                                         unsigned a0, unsigned a1, unsigned a2, unsigned a3,
                                         unsigned b0, unsigned b1)
{
    asm volatile(
        "mma.sync.aligned.m16n8k8.row.col.f32.tf32.tf32.f32 "
        "{%0,%1,%2,%3}, {%4,%5,%6,%7}, {%8,%9}, {%0,%1,%2,%3};"
        : "+f"(d0), "+f"(d1), "+f"(d2), "+f"(d3)
        : "r"(a0), "r"(a1), "r"(a2), "r"(a3), "r"(b0), "r"(b1));
}

// ---------------------------------------------------------------------------
// Sync gate: sw = sigmoid(relu(sf @ Ws1 + bs1) @ Ws2 + bs2)   [B,H]
// ---------------------------------------------------------------------------
__global__ void gate_kernel(const float* __restrict__ sf,
                            const float* __restrict__ Ws1, const float* __restrict__ bs1,
                            const float* __restrict__ Ws2, const float* __restrict__ bs2)
{
    __shared__ float h1[BATCH*HIDG];
    int tid = threadIdx.x;
    for (int idx = tid; idx < BATCH*HIDG; idx += blockDim.x) {
        int b = idx / HIDG, j = idx % HIDG;
        float acc = bs1[j];
        for (int k = 0; k < EMB; k++)
            acc += sf[b*EMB + k] * Ws1[k*HIDG + j];
        h1[idx] = fmaxf(acc, 0.0f);
    }
    __syncthreads();
    if (tid < BATCH*NH) {
        int b = tid / NH, h = tid % NH;
        float acc = bs2[h];
        for (int j = 0; j < HIDG; j++)
            acc += h1[b*HIDG + j] * Ws2[j*NH + h];
        g_sw[tid] = 1.0f / (1.0f + expf(-acc));
    }
}

// ---------------------------------------------------------------------------
// TF32 tensor-core GEMM body: C[M,N] = X[M,K] @ W[K,N] + bias
// Block tile 128x128, BK=32, 256 threads (8 warps as 2(m) x 4(n)),
// warp tile 64x32 = 4x4 m16n8k8 mma tiles.
// ---------------------------------------------------------------------------
#define GPA 36    // A smem pitch (floats): bank-conflict-free fragment loads
#define GPB 136   // B smem pitch

__device__ __forceinline__ void gemm_tf32_body(
    const float* __restrict__ X, const float* __restrict__ W,
    const float* __restrict__ bias, float* __restrict__ C,
    int M, int N, int K)
{
    __shared__ unsigned As[128*GPA];
    __shared__ unsigned Bs[32*GPB];

    const int tid  = threadIdx.x;
    const int warp = tid >> 5, lane = tid & 31;
    const int g = lane >> 2, t = lane & 3;
    const int wm = warp & 1, wn = warp >> 1;      // 2 x 4 warp grid
    const int m0 = blockIdx.y * 128, n0 = blockIdx.x * 128;

    const int ar_row = tid >> 3, ar_c4 = (tid & 7) << 2;    // A: 4 passes of 32 rows
    const int br_row = tid >> 5, br_c4 = (tid & 31) << 2;   // B: 4 passes of 8 rows

    float4 ar[4], br[4];
    float acc[4][4][4] = {};

    // prologue: load first tile to regs
    #pragma unroll
    for (int p = 0; p < 4; p++)
        ar[p] = *(const float4*)&X[(size_t)(m0 + ar_row + p*32)*K + ar_c4];
    #pragma unroll
    for (int p = 0; p < 4; p++)
        br[p] = *(const float4*)&W[(size_t)(br_row + p*8)*N + n0 + br_c4];

    for (int k0 = 0; k0 < K; k0 += 32) {
        // store regs -> smem (tf32 rounded)
        #pragma unroll
        for (int p = 0; p < 4; p++) {
            unsigned* d = &As[(ar_row + p*32)*GPA + ar_c4];
            d[0] = f2tf(ar[p].x); d[1] = f2tf(ar[p].y);
            d[2] = f2tf(ar[p].z); d[3] = f2tf(ar[p].w);
        }
        #pragma unroll
        for (int p = 0; p < 4; p++) {
            unsigned* d = &Bs[(br_row + p*8)*GPB + br_c4];
            d[0] = f2tf(br[p].x); d[1] = f2tf(br[p].y);
            d[2] = f2tf(br[p].z); d[3] = f2tf(br[p].w);
        }
        __syncthreads();

        // prefetch next tile
        if (k0 + 32 < K) {
            #pragma unroll
            for (int p = 0; p < 4; p++)
                ar[p] = *(const float4*)&X[(size_t)(m0 + ar_row + p*32)*K + k0 + 32 + ar_c4];
            #pragma unroll
            for (int p = 0; p < 4; p++)
                br[p] = *(const float4*)&W[(size_t)(k0 + 32 + br_row + p*8)*N + n0 + br_c4];
        }

        // compute 4 k-steps of 8
        #pragma unroll
        for (int ks = 0; ks < 4; ks++) {
            unsigned af[4][4], bf[4][2];
            #pragma unroll
            for (int mt = 0; mt < 4; mt++) {
                int row = wm*64 + mt*16 + g;
                af[mt][0] = As[row*GPA + ks*8 + t];
                af[mt][1] = As[(row+8)*GPA + ks*8 + t];
                af[mt][2] = As[row*GPA + ks*8 + t + 4];
                af[mt][3] = As[(row+8)*GPA + ks*8 + t + 4];
            }
            #pragma unroll
            for (int nt = 0; nt < 4; nt++) {
                int col = wn*32 + nt*8 + g;
                bf[nt][0] = Bs[(ks*8 + t)*GPB + col];
                bf[nt][1] = Bs[(ks*8 + t + 4)*GPB + col];
            }
            #pragma unroll
            for (int mt = 0; mt < 4; mt++)
                #pragma unroll
                for (int nt = 0; nt < 4; nt++)
                    mma_tf32(acc[mt][nt][0], acc[mt][nt][1], acc[mt][nt][2], acc[mt][nt][3],
                             af[mt][0], af[mt][1], af[mt][2], af[mt][3],
                             bf[nt][0], bf[nt][1]);
        }
        __syncthreads();
    }

    // epilogue: add bias, store
    #pragma unroll
    for (int nt = 0; nt < 4; nt++) {
        int col = n0 + wn*32 + nt*8 + 2*t;
        float2 bv = *(const float2*)&bias[col];
        #pragma unroll
        for (int mt = 0; mt < 4; mt++) {
            int row = m0 + wm*64 + mt*16 + g;
            float2 o0 = { acc[mt][nt][0] + bv.x, acc[mt][nt][1] + bv.y };
            float2 o1 = { acc[mt][nt][2] + bv.x, acc[mt][nt][3] + bv.y };
            *(float2*)&C[(size_t)row*N + col]     = o0;
            *(float2*)&C[(size_t)(row+8)*N + col] = o1;
        }
    }
}

// single GEMM (output projection)
__global__ void __launch_bounds__(256, 2) gemm_tf32_kernel(
    const float* __restrict__ X, const float* __restrict__ W,
    const float* __restrict__ bias, float* __restrict__ C,
    int M, int N, int K)
{
    gemm_tf32_body(X, W, bias, C, M, N, K);
}

// fused QKV: blockIdx.z selects projection (0=Q, 1=K, 2=V)
__global__ void __launch_bounds__(256, 2) gemm_qkv_kernel(
    const float* __restrict__ X,
    const float* __restrict__ Wq, const float* __restrict__ bq,
    const float* __restrict__ Wk, const float* __restrict__ bk,
    const float* __restrict__ Wv, const float* __restrict__ bv,
    float* __restrict__ q, float* __restrict__ k, float* __restrict__ v)
{
    const float* W; const float* bias; float* C;
    if (blockIdx.z == 0)      { W = Wq; bias = bq; C = q; }
    else if (blockIdx.z == 1) { W = Wk; bias = bk; C = k; }
    else                      { W = Wv; bias = bv; C = v; }
    gemm_tf32_body(X, W, bias, C, MROWS, EMB, EMB);
}

// ---------------------------------------------------------------------------
// Attention with tf32 tensor cores.
// Block = (b, h, 128-row i-tile), 256 threads (8 warps as 4(m) x 2(n)).
// Per j-tile of 64: S = Q K^T (mma), p = rna_tf32(exp(sl*S)) used consistently
// for row sums, smem P, g_p scratch, and the PV MMA. Finalize ctx /= l.
// K/V tiles are prefetched into registers during the PV MMA phase; 2 CTAs/SM.
// ---------------------------------------------------------------------------
#define PQ 68
#define PK 68
#define PV 72
#define PP 68
#define ATTN_SMEM_BYTES ((128*PQ + 64*PK + 64*PV + 128*PP + 128) * 4)

__global__ void __launch_bounds__(256, 2) attn_kernel()
{
    extern __shared__ unsigned char smraw[];
    unsigned* Qs = (unsigned*)smraw;               // [128][PQ] tf32 bits
    unsigned* Ks = Qs + 128*PQ;                    // [64][PK]
    unsigned* Vs = Ks + 64*PK;                     // [64][PV]
    float*    Ps = (float*)(Vs + 64*PV);           // [128][PP] probs (tf32 values)
    float*  l_sm = Ps + 128*PP;                    // [128]

    const int tid  = threadIdx.x;
    const int warp = tid >> 5, lane = tid & 31;
    const int g = lane >> 2, t = lane & 3;
    const int wm = warp & 3, wn = warp >> 2;       // 4 x 2 warp grid
    const int i0 = blockIdx.x * 128, h = blockIdx.y, b = blockIdx.z;

    const float sl = g_sw[b*NH + h] * 0.125f;      // sw / sqrt(DH)

    const float* qbase = g_q + ((size_t)(b*SEQ + i0))*EMB + h*DHEAD;
    const float* kbase = g_k + ((size_t)(b*SEQ))*EMB + h*DHEAD;
    const float* vbase = g_v + ((size_t)(b*SEQ))*EMB + h*DHEAD;
    float*       pbase = g_p + ((size_t)(b*NH + h)*SEQ + i0)*SEQ;

    // per-thread KV load coordinates (4 passes of 16 rows each)
    const int kv_r  = tid >> 4;            // 0..15
    const int kv_c4 = (tid & 15) << 2;     // 0..60

    // load Q tile [128][64] -> tf32 smem
    #pragma unroll
    for (int p = 0; p < 8; p++) {
        int idx = tid + p*256;
        int r = idx >> 4, c4 = (idx & 15) << 2;
        float4 v = *(const float4*)&qbase[(size_t)r*EMB + c4];
        unsigned* d = &Qs[r*PQ + c4];
        d[0] = f2tf(v.x); d[1] = f2tf(v.y); d[2] = f2tf(v.z); d[3] = f2tf(v.w);
    }
    if (tid < 128) l_sm[tid] = 0.0f;

    float cacc[2][4][4] = {};    // ctx accumulators (mt, nt, c)
    float ls[4] = {};            // row-sum accumulators

    // prologue: prefetch first K/V tile into registers
    float4 kvr[4], vvr[4];
    #pragma unroll
    for (int p = 0; p < 4; p++) {
        kvr[p] = *(const float4*)&kbase[(size_t)(kv_r + p*16)*EMB + kv_c4];
        vvr[p] = *(const float4*)&vbase[(size_t)(kv_r + p*16)*EMB + kv_c4];
    }
    __syncthreads();

    for (int j0 = 0; j0 < SEQ; j0 += 64) {
        // store prefetched K, V regs -> tf32 smem
        #pragma unroll
        for (int p = 0; p < 4; p++) {
            int r = kv_r + p*16;
            unsigned* dk = &Ks[r*PK + kv_c4];
            dk[0] = f2tf(kvr[p].x); dk[1] = f2tf(kvr[p].y);
            dk[2] = f2tf(kvr[p].z); dk[3] = f2tf(kvr[p].w);
            unsigned* dv = &Vs[r*PV + kv_c4];
            dv[0] = f2tf(vvr[p].x); dv[1] = f2tf(vvr[p].y);
            dv[2] = f2tf(vvr[p].z); dv[3] = f2tf(vvr[p].w);
        }
        __syncthreads();

        // S = Q K^T : warp tile 32(i) x 32(j) = 2 x 4 mma tiles, k = 64
        float sacc[2][4][4] = {};
        #pragma unroll
        for (int ks = 0; ks < 8; ks++) {
            unsigned af[2][4], bf[4][2];
            #pragma unroll
            for (int mt = 0; mt < 2; mt++) {
                int row = wm*32 + mt*16 + g;
                af[mt][0] = Qs[row*PQ + ks*8 + t];
                af[mt][1] = Qs[(row+8)*PQ + ks*8 + t];
                af[mt][2] = Qs[row*PQ + ks*8 + t + 4];
                af[mt][3] = Qs[(row+8)*PQ + ks*8 + t + 4];
            }
            #pragma unroll
            for (int nt = 0; nt < 4; nt++) {
                int jc = wn*32 + nt*8 + g;
                bf[nt][0] = Ks[jc*PK + ks*8 + t];
                bf[nt][1] = Ks[jc*PK + ks*8 + t + 4];
            }
            #pragma unroll
            for (int mt = 0; mt < 2; mt++)
                #pragma unroll
                for (int nt = 0; nt < 4; nt++)
                    mma_tf32(sacc[mt][nt][0], sacc[mt][nt][1], sacc[mt][nt][2], sacc[mt][nt][3],
                             af[mt][0], af[mt][1], af[mt][2], af[mt][3],
                             bf[nt][0], bf[nt][1]);
        }

        // p = exp(sl*S), rounded once to tf32 and used consistently everywhere
        #pragma unroll
        for (int mt = 0; mt < 2; mt++) {
            #pragma unroll
            for (int nt = 0; nt < 4; nt++) {
                float p0 = __uint_as_float(f2tf(__expf(sacc[mt][nt][0] * sl)));
                float p1 = __uint_as_float(f2tf(__expf(sacc[mt][nt][1] * sl)));
                float p2 = __uint_as_float(f2tf(__expf(sacc[mt][nt][2] * sl)));
                float p3 = __uint_as_float(f2tf(__expf(sacc[mt][nt][3] * sl)));
                ls[mt*2 + 0] += p0 + p1;
                ls[mt*2 + 1] += p2 + p3;
                int row = wm*32 + mt*16 + g;
                int col = wn*32 + nt*8 + 2*t;
                *(float2*)&Ps[row*PP + col]     = make_float2(p0, p1);
                *(float2*)&Ps[(row+8)*PP + col] = make_float2(p2, p3);
                *(float2*)&pbase[(size_t)row*SEQ + j0 + col]     = make_float2(p0, p1);
                *(float2*)&pbase[(size_t)(row+8)*SEQ + j0 + col] = make_float2(p2, p3);
            }
        }
        __syncthreads();

        // prefetch next K/V tile into registers (overlaps with PV MMA below)
        if (j0 + 64 < SEQ) {
            #pragma unroll
            for (int p = 0; p < 4; p++) {
                kvr[p] = *(const float4*)&kbase[(size_t)(j0 + 64 + kv_r + p*16)*EMB + kv_c4];
                vvr[p] = *(const float4*)&vbase[(size_t)(j0 + 64 + kv_r + p*16)*EMB + kv_c4];
            }
        }

        // ctx += P V : warp tile 32(i) x 32(d) = 2 x 4 mma tiles, k = 64 (j)
        #pragma unroll
        for (int ks = 0; ks < 8; ks++) {
            unsigned af[2][4], bf[4][2];
            #pragma unroll
            for (int mt = 0; mt < 2; mt++) {
                int row = wm*32 + mt*16 + g;
                af[mt][0] = __float_as_uint(Ps[row*PP + ks*8 + t]);
                af[mt][1] = __float_as_uint(Ps[(row+8)*PP + ks*8 + t]);
                af[mt][2] = __float_as_uint(Ps[row*PP + ks*8 + t + 4]);
                af[mt][3] = __float_as_uint(Ps[(row+8)*PP + ks*8 + t + 4]);
            }
            #pragma unroll
            for (int nt = 0; nt < 4; nt++) {
                int dc = wn*32 + nt*8 + g;
                bf[nt][0] = Vs[(ks*8 + t)*PV + dc];
                bf[nt][1] = Vs[(ks*8 + t + 4)*PV + dc];
            }
            #pragma unroll
            for (int mt = 0; mt < 2; mt++)
                #pragma unroll
                for (int nt = 0; nt < 4; nt++)
                    mma_tf32(cacc[mt][nt][0], cacc[mt][nt][1], cacc[mt][nt][2], cacc[mt][nt][3],
                             af[mt][0], af[mt][1], af[mt][2], af[mt][3],
                             bf[nt][0], bf[nt][1]);
        }
        __syncthreads();
    }

    // reduce row sums across the quad (t lanes), accumulate into l_sm
    #pragma unroll
    for (int i = 0; i < 4; i++) {
        float v = ls[i];
        v += __shfl_xor_sync(0xffffffffu, v, 1);
        v += __shfl_xor_sync(0xffffffffu, v, 2);
        ls[i] = v;
    }
    if (t == 0) {
        #pragma unroll
        for (int mt = 0; mt < 2; mt++) {
            int row = wm*32 + mt*16 + g;
            atomicAdd(&l_sm[row],     ls[mt*2 + 0]);
            atomicAdd(&l_sm[row + 8], ls[mt*2 + 1]);
        }
    }
    __syncthreads();

    // finalize: ctx /= l, store ctx and l
    float* cbase = g_ctx + ((size_t)(b*SEQ + i0))*EMB + h*DHEAD;
    #pragma unroll
    for (int mt = 0; mt < 2; mt++) {
        int row = wm*32 + mt*16 + g;
        float inv0 = 1.0f / l_sm[row];
        float inv1 = 1.0f / l_sm[row + 8];
        #pragma unroll
        for (int nt = 0; nt < 4; nt++) {
            int col = wn*32 + nt*8 + 2*t;
            float2 o0 = { cacc[mt][nt][0]*inv0, cacc[mt][nt][1]*inv0 };
            float2 o1 = { cacc[mt][nt][2]*inv1, cacc[mt][nt][3]*inv1 };
            *(float2*)&cbase[(size_t)row*EMB + col]     = o0;
            *(float2*)&cbase[(size_t)(row+8)*EMB + col] = o1;
        }
    }
    if (tid < 128)
        g_l[(size_t)(b*NH + h)*SEQ + i0 + tid] = l_sm[tid];
}

// ---------------------------------------------------------------------------
// mean[b,i,j] = (1/H) * sum_h g_p[b,h,i,j] / g_l[b,h,i]
// ---------------------------------------------------------------------------
__global__ void __launch_bounds__(256) mean_kernel(float* __restrict__ out_mean)
{
    const int i = blockIdx.x, b = blockIdx.y;
    const int tid = threadIdx.x;
    __shared__ float inv[NH];
    if (tid < NH)
        inv[tid] = 1.0f / (g_l[(size_t)(b*NH + tid)*SEQ + i] * (float)NH);
    __syncthreads();

    float4 a0 = {0,0,0,0}, a1 = {0,0,0,0};
    #pragma unroll
    for (int h = 0; h < NH; h++) {
        const float4* p4 = (const float4*)&g_p[((size_t)(b*NH + h)*SEQ + i)*SEQ];
        float4 v0 = p4[tid];
        float4 v1 = p4[tid + 256];
        float w = inv[h];
        a0.x += v0.x*w; a0.y += v0.y*w; a0.z += v0.z*w; a0.w += v0.w*w;
        a1.x += v1.x*w; a1.y += v1.y*w; a1.z += v1.z*w; a1.w += v1.w*w;
    }
    float4* dst = (float4*)&out_mean[((size_t)(b*SEQ) + i)*SEQ];
    dst[tid]       = a0;
    dst[tid + 256] = a1;
}

// ---------------------------------------------------------------------------
extern "C" void kernel_launch(void* const* d_in, const int* in_sizes, int n_in,
                              void* d_out, int out_size)
{
    const float* x   = (const float*)d_in[0];
    const float* sf  = (const float*)d_in[1];
    const float* Wq  = (const float*)d_in[2];  const float* bq  = (const float*)d_in[3];
    const float* Wk  = (const float*)d_in[4];  const float* bk  = (const float*)d_in[5];
    const float* Wv  = (const float*)d_in[6];  const float* bv  = (const float*)d_in[7];
    const float* Ws1 = (const float*)d_in[8];  const float* bs1 = (const float*)d_in[9];
    const float* Ws2 = (const float*)d_in[10]; const float* bs2 = (const float*)d_in[11];
    const float* Wo  = (const float*)d_in[12]; const float* bo  = (const float*)d_in[13];

    float* out      = (float*)d_out;                       // [B,S,E]
    float* out_mean = out + (size_t)BATCH*SEQ*EMB;         // [B,S,S]

    float *qp, *kp, *vp, *cp;
    cudaGetSymbolAddress((void**)&qp, g_q);
    cudaGetSymbolAddress((void**)&kp, g_k);
    cudaGetSymbolAddress((void**)&vp, g_v);
    cudaGetSymbolAddress((void**)&cp, g_ctx);

    cudaFuncSetAttribute(attn_kernel,
                         cudaFuncAttributeMaxDynamicSharedMemorySize,
                         ATTN_SMEM_BYTES);

    // 1) sync gate
    gate_kernel<<<1, 256>>>(sf, Ws1, bs1, Ws2, bs2);

    // 2) fused QKV projections (tf32 tensor cores), one launch
    dim3 gq(EMB/128, MROWS/128, 3);
    gemm_qkv_kernel<<<gq, 256>>>(x, Wq, bq, Wk, bk, Wv, bv, qp, kp, vp);

    // 3) attention (ctx, p scratch, denominators)
    attn_kernel<<<dim3(SEQ/128, NH, BATCH), 256, ATTN_SMEM_BYTES>>>();

    // 4) head-mean of attention probs
    mean_kernel<<<dim3(SEQ, BATCH), 256>>>(out_mean);

    // 5) output projection
    dim3 gg(EMB/128, MROWS/128);
    gemm_tf32_kernel<<<gg, 256>>>(cp, Wo, bo, out, MROWS, EMB, EMB);
}